// round 10
// baseline (speedup 1.0000x reference)
#include <cuda_runtime.h>
#include <cuda_fp16.h>
#include <cstdint>

#define N_NODES 50000
#define N_EDGES 600000
#define DIM 128

// Scratch
__device__ float g_denom[N_NODES];
__device__ __half2 g_embh[N_NODES * 64];  // fp16 mirror of emb (12.8MB)

// ---------------------------------------------------------------------------
// helpers
// ---------------------------------------------------------------------------
__device__ __forceinline__ uint32_t pack2h(float x0, float x1) {
    uint32_t d;
    asm("cvt.rn.f16x2.f32 %0, %1, %2;" : "=r"(d) : "f"(x1), "f"(x0));
    return d;
}
__device__ __forceinline__ uint32_t smem_u32(const void* p) {
    uint32_t a;
    asm("{ .reg .u64 t; cvta.to.shared.u64 t, %1; cvt.u32.u64 %0, t; }"
        : "=r"(a) : "l"(p));
    return a;
}
__device__ __forceinline__ void mma_fp16(float* c, uint32_t a0, uint32_t a1,
                                         uint32_t a2, uint32_t a3,
                                         uint32_t b0, uint32_t b1) {
    asm volatile(
        "mma.sync.aligned.m16n8k16.row.col.f32.f16.f16.f32 "
        "{%0,%1,%2,%3}, {%4,%5,%6,%7}, {%8,%9}, {%0,%1,%2,%3};"
        : "+f"(c[0]), "+f"(c[1]), "+f"(c[2]), "+f"(c[3])
        : "r"(a0), "r"(a1), "r"(a2), "r"(a3), "r"(b0), "r"(b1));
}
__device__ __forceinline__ void ldsm_x4(uint32_t* r, uint32_t addr) {
    asm volatile(
        "ldmatrix.sync.aligned.m8n8.x4.shared.b16 {%0,%1,%2,%3}, [%4];"
        : "=r"(r[0]), "=r"(r[1]), "=r"(r[2]), "=r"(r[3]) : "r"(addr));
}

// ---------------------------------------------------------------------------
__global__ void dummy_kernel() {}

// K-conv: build fp16 mirror of emb
__global__ void conv_kernel(const float4* __restrict__ emb4) {
    int idx = blockIdx.x * blockDim.x + threadIdx.x;
    int stride = gridDim.x * blockDim.x;
    const int n = N_NODES * 32;  // float4 count
    uint2* dst = reinterpret_cast<uint2*>(g_embh);
    for (int i = idx; i < n; i += stride) {
        float4 v = emb4[i];
        dst[i] = make_uint2(pack2h(v.x, v.y), pack2h(v.z, v.w));
    }
}

// K0: zero agg (d_out) + denom
__global__ void zero_kernel(float4* __restrict__ out4) {
    int idx = blockIdx.x * blockDim.x + threadIdx.x;
    int stride = gridDim.x * blockDim.x;
    const int n4 = N_NODES * DIM / 4;
    float4 z = make_float4(0.f, 0.f, 0.f, 0.f);
    for (int i = idx; i < n4; i += stride) out4[i] = z;
    for (int i = idx; i < N_NODES; i += stride) g_denom[i] = 0.f;
}

// ---------------------------------------------------------------------------
// K1: 4 edges/warp (8 lanes each), fp16 gathers (halves gather bytes),
// fp32 dot + red.v4.
// ---------------------------------------------------------------------------
__global__ void edge_kernel(const int* __restrict__ edges,
                            float* __restrict__ agg) {
    int gwarp = (blockIdx.x * blockDim.x + threadIdx.x) >> 5;
    int lane = threadIdx.x & 31;
    int q = lane >> 3;
    int ql = lane & 7;

    int e = gwarp * 4 + q;
    if (e >= N_EDGES) return;

    int r = edges[e];
    int c = edges[N_EDGES + e];
    if ((unsigned)r >= N_NODES || (unsigned)c >= N_NODES) return;

    const uint4* ar = reinterpret_cast<const uint4*>(g_embh + (size_t)r * 64);
    const uint4* br = reinterpret_cast<const uint4*>(g_embh + (size_t)c * 64);
    uint4 A0 = ar[ql], A1 = ar[ql + 8];
    uint4 B0 = br[ql], B1 = br[ql + 8];

    float bf[16];
    float p = 0.f;
    {
        const __half2* ha = reinterpret_cast<const __half2*>(&A0);
        const __half2* hb = reinterpret_cast<const __half2*>(&B0);
#pragma unroll
        for (int j = 0; j < 4; j++) {
            float2 fa = __half22float2(ha[j]);
            float2 fb = __half22float2(hb[j]);
            bf[2 * j] = fb.x;
            bf[2 * j + 1] = fb.y;
            p = fmaf(fa.x, fb.x, p);
            p = fmaf(fa.y, fb.y, p);
        }
        const __half2* ha1 = reinterpret_cast<const __half2*>(&A1);
        const __half2* hb1 = reinterpret_cast<const __half2*>(&B1);
#pragma unroll
        for (int j = 0; j < 4; j++) {
            float2 fa = __half22float2(ha1[j]);
            float2 fb = __half22float2(hb1[j]);
            bf[8 + 2 * j] = fb.x;
            bf[8 + 2 * j + 1] = fb.y;
            p = fmaf(fa.x, fb.x, p);
            p = fmaf(fa.y, fb.y, p);
        }
    }
#pragma unroll
    for (int o = 4; o > 0; o >>= 1)
        p += __shfl_xor_sync(0xffffffffu, p, o);

    float w = expf(p);
    if (ql == 0) atomicAdd(&g_denom[r], w);

    float* base = agg + (size_t)r * DIM;
#pragma unroll
    for (int h = 0; h < 2; h++) {
        float* dst = base + h * 64 + 8 * ql;
        const float* s = bf + 8 * h;
        asm volatile("red.global.add.v4.f32 [%0], {%1, %2, %3, %4};"
                     :: "l"(dst), "f"(w * s[0]), "f"(w * s[1]),
                        "f"(w * s[2]), "f"(w * s[3]) : "memory");
        asm volatile("red.global.add.v4.f32 [%0], {%1, %2, %3, %4};"
                     :: "l"(dst + 4), "f"(w * s[4]), "f"(w * s[5]),
                        "f"(w * s[6]), "f"(w * s[7]) : "memory");
    }
}

// ---------------------------------------------------------------------------
// K2: fp16 2-term MMA GEMM + LN, fragments via ldmatrix.x4.
//   D = xh*fp16(W) + (256*xl)*fp16(W/256)
// ---------------------------------------------------------------------------
#define TILE_R 64
#define WSTRIDE 132
#define SM_WPH 0
#define SM_WP2 (128 * WSTRIDE)
#define SM_XPH (2 * 128 * WSTRIDE)
#define SM_XP2 (2 * 128 * WSTRIDE + 64 * WSTRIDE)
#define SMEM_WORDS (2 * 128 * WSTRIDE + 2 * 64 * WSTRIDE)
#define GEMM_SMEM_BYTES (SMEM_WORDS * 4)

__global__ void __launch_bounds__(256, 1)
gemm_ln_kernel(const float* __restrict__ emb,
               const float* __restrict__ W,
               const float* __restrict__ bias,
               const float* __restrict__ gamma,
               const float* __restrict__ beta,
               float* __restrict__ out) {
    extern __shared__ uint32_t smem[];
    uint32_t* Wph = smem + SM_WPH;
    uint32_t* Wp2 = smem + SM_WP2;
    uint32_t* xph = smem + SM_XPH;
    uint32_t* xp2 = smem + SM_XP2;
    float* os = reinterpret_cast<float*>(smem + SM_XPH);

    const int tid = threadIdx.x;
    const int lane = tid & 31;
    const int wid = tid >> 5;
    const int g = lane >> 2;
    const int tig = lane & 3;

    for (int idx = tid; idx < 128 * 128; idx += 256) {
        int n = idx >> 7;
        int k2 = idx & 127;
        float2 w2 = *reinterpret_cast<const float2*>(&W[n * 256 + 2 * k2]);
        Wph[n * WSTRIDE + k2] = pack2h(w2.x, w2.y);
        Wp2[n * WSTRIDE + k2] =
            pack2h(w2.x * (1.0f / 256.0f), w2.y * (1.0f / 256.0f));
    }
    __syncthreads();

    const int mwarp = wid & 3;
    const int nwarp = wid >> 2;
    const int n0 = nwarp * 64;

    // ---- ldmatrix base addresses (byte) ----
    const uint32_t sb = smem_u32(smem);
    const int rowA = mwarp * 16 + (lane & 15);
    const int colwA = (lane >> 4) * 4;  // words
    const uint32_t aAh0 = sb + (SM_XPH + rowA * WSTRIDE + colwA) * 4;
    const uint32_t aA20 = sb + (SM_XP2 + rowA * WSTRIDE + colwA) * 4;
    const int rowB = n0 + (lane & 7) + ((lane & 16) >> 1);
    const int colwB = ((lane >> 3) & 1) * 4;
    const uint32_t aBh0 = sb + (SM_WPH + rowB * WSTRIDE + colwB) * 4;
    const uint32_t aB20 = sb + (SM_WP2 + rowB * WSTRIDE + colwB) * 4;
    const uint32_t NTP_STEP = 16 * WSTRIDE * 4;  // 16 rows

    const int ntiles = (N_NODES + TILE_R - 1) / TILE_R;
    for (int tile = blockIdx.x; tile < ntiles; tile += gridDim.x) {
        const int row0 = tile * TILE_R;

        // ---- stage x tile ----
#pragma unroll
        for (int i = 0; i < 8; i++) {
            int r = wid * 8 + i;
            int row = row0 + r;
            float4 e4, a4;
            if (row < N_NODES) {
                e4 = reinterpret_cast<const float4*>(emb)[(size_t)row * 32 + lane];
                float inv_d = 1.0f / (g_denom[row] + 1e-20f);
                a4 = reinterpret_cast<const float4*>(out)[(size_t)row * 32 + lane];
                a4.x *= inv_d; a4.y *= inv_d; a4.z *= inv_d; a4.w *= inv_d;
            } else {
                e4 = make_float4(0.f, 0.f, 0.f, 0.f);
                a4 = e4;
            }
            float ex = __half2float(__float2half_rn(e4.x));
            float ey = __half2float(__float2half_rn(e4.y));
            float ez = __half2float(__float2half_rn(e4.z));
            float ew = __half2float(__float2half_rn(e4.w));
            xph[r * WSTRIDE + 2 * lane] = pack2h(ex, ey);
            xph[r * WSTRIDE + 2 * lane + 1] = pack2h(ez, ew);
            xp2[r * WSTRIDE + 2 * lane] =
                pack2h((e4.x - ex) * 256.0f, (e4.y - ey) * 256.0f);
            xp2[r * WSTRIDE + 2 * lane + 1] =
                pack2h((e4.z - ez) * 256.0f, (e4.w - ew) * 256.0f);

            float ax = __half2float(__float2half_rn(a4.x));
            float ay = __half2float(__float2half_rn(a4.y));
            float az = __half2float(__float2half_rn(a4.z));
            float aw = __half2float(__float2half_rn(a4.w));
            xph[r * WSTRIDE + 64 + 2 * lane] = pack2h(ax, ay);
            xph[r * WSTRIDE + 64 + 2 * lane + 1] = pack2h(az, aw);
            xp2[r * WSTRIDE + 64 + 2 * lane] =
                pack2h((a4.x - ax) * 256.0f, (a4.y - ay) * 256.0f);
            xp2[r * WSTRIDE + 64 + 2 * lane + 1] =
                pack2h((a4.z - az) * 256.0f, (a4.w - aw) * 256.0f);
        }
        __syncthreads();

        // ---- mma mainloop with ldmatrix fragments ----
        float acc[8][4];
#pragma unroll
        for (int nt = 0; nt < 8; nt++)
#pragma unroll
            for (int qq = 0; qq < 4; qq++) acc[nt][qq] = 0.f;

        uint32_t aAh = aAh0, aA2 = aA20, aBh = aBh0, aB2 = aB20;
#pragma unroll
        for (int ks = 0; ks < 16; ks++) {
            uint32_t ah[4], al[4];
            ldsm_x4(ah, aAh);
            ldsm_x4(al, aA2);
            aAh += 32; aA2 += 32;
#pragma unroll
            for (int ntp = 0; ntp < 4; ntp++) {
                uint32_t bh[4], b2[4];
                ldsm_x4(bh, aBh + ntp * NTP_STEP);
                ldsm_x4(b2, aB2 + ntp * NTP_STEP);
                mma_fp16(acc[2 * ntp], ah[0], ah[1], ah[2], ah[3], bh[0], bh[1]);
                mma_fp16(acc[2 * ntp + 1], ah[0], ah[1], ah[2], ah[3], bh[2], bh[3]);
                mma_fp16(acc[2 * ntp], al[0], al[1], al[2], al[3], b2[0], b2[1]);
                mma_fp16(acc[2 * ntp + 1], al[0], al[1], al[2], al[3], b2[2], b2[3]);
            }
            aBh += 32; aB2 += 32;
        }
        __syncthreads();

        // ---- write accums to smem [64][128] ----
#pragma unroll
        for (int nt = 0; nt < 8; nt++) {
            int ccol = n0 + nt * 8 + 2 * tig;
            int crow = mwarp * 16 + g;
            *reinterpret_cast<float2*>(&os[crow * 128 + ccol]) =
                make_float2(acc[nt][0], acc[nt][1]);
            *reinterpret_cast<float2*>(&os[(crow + 8) * 128 + ccol]) =
                make_float2(acc[nt][2], acc[nt][3]);
        }
        __syncthreads();

        // ---- LayerNorm ----
        const float4 b4 = reinterpret_cast<const float4*>(bias)[lane];
        const float4 g4 = reinterpret_cast<const float4*>(gamma)[lane];
        const float4 be4 = reinterpret_cast<const float4*>(beta)[lane];
#pragma unroll
        for (int i = 0; i < 8; i++) {
            int r = wid * 8 + i;
            int row = row0 + r;
            float4 v = reinterpret_cast<float4*>(os)[r * 32 + lane];
            v.x += b4.x; v.y += b4.y; v.z += b4.z; v.w += b4.w;
            float s = v.x + v.y + v.z + v.w;
            float sq = v.x * v.x + v.y * v.y + v.z * v.z + v.w * v.w;
#pragma unroll
            for (int o = 16; o > 0; o >>= 1) {
                s += __shfl_xor_sync(0xffffffffu, s, o);
                sq += __shfl_xor_sync(0xffffffffu, sq, o);
            }
            float mu = s * (1.0f / 128.0f);
            float var = sq * (1.0f / 128.0f) - mu * mu;
            float rs = rsqrtf(var + 1e-5f);
            if (row < N_NODES) {
                float4 o4;
                o4.x = (v.x - mu) * rs * g4.x + be4.x;
                o4.y = (v.y - mu) * rs * g4.y + be4.y;
                o4.z = (v.z - mu) * rs * g4.z + be4.z;
                o4.w = (v.w - mu) * rs * g4.w + be4.w;
                reinterpret_cast<float4*>(out)[(size_t)row * 32 + lane] = o4;
            }
        }
        __syncthreads();
    }
}

// ---------------------------------------------------------------------------
extern "C" void kernel_launch(void* const* d_in, const int* in_sizes, int n_in,
                              void* d_out, int out_size) {
    const float* emb = (const float*)d_in[0];
    const int* edges = (const int*)d_in[1];  // int32 (JAX x64 disabled)
    const float* W = (const float*)d_in[2];
    const float* bias = (const float*)d_in[3];
    const float* gamma = (const float*)d_in[4];
    const float* beta = (const float*)d_in[5];
    float* out = (float*)d_out;

    (void)in_sizes; (void)n_in; (void)out_size;

    // ncu captures global launch #4 -> keep edge_kernel there.
    conv_kernel<<<2048, 256>>>(reinterpret_cast<const float4*>(emb));  // #1
    zero_kernel<<<4096, 256>>>(reinterpret_cast<float4*>(out));        // #2
    dummy_kernel<<<1, 32>>>();                                         // #3

    {  // #4: edge kernel, 4 edges per warp, fp16 gathers
        int nwarps = N_EDGES / 4;
        int blocks = (nwarps * 32 + 255) / 256;
        edge_kernel<<<blocks, 256>>>(edges, out);
    }

    // #5: GEMM + LN
    cudaFuncSetAttribute(gemm_ln_kernel,
                         cudaFuncAttributeMaxDynamicSharedMemorySize,
                         GEMM_SMEM_BYTES);
    gemm_ln_kernel<<<148, 256, GEMM_SMEM_BYTES>>>(emb, W, bias, gamma, beta,
                                                  out);
}

// round 11
// speedup vs baseline: 1.2532x; 1.2532x over previous
#include <cuda_runtime.h>
#include <cuda_fp16.h>
#include <cstdint>

#define N_NODES 50000
#define N_EDGES 600000
#define DIM 128

__device__ float g_denom[N_NODES];

// ---------------------------------------------------------------------------
// helpers
// ---------------------------------------------------------------------------
__device__ __forceinline__ uint32_t pack2h(float x0, float x1) {
    uint32_t d;
    asm("cvt.rn.f16x2.f32 %0, %1, %2;" : "=r"(d) : "f"(x1), "f"(x0));
    return d;
}
__device__ __forceinline__ uint32_t smem_u32(const void* p) {
    uint32_t a;
    asm("{ .reg .u64 t; cvta.to.shared.u64 t, %1; cvt.u32.u64 %0, t; }"
        : "=r"(a) : "l"(p));
    return a;
}
__device__ __forceinline__ void mma_fp16(float* c, uint32_t a0, uint32_t a1,
                                         uint32_t a2, uint32_t a3,
                                         uint32_t b0, uint32_t b1) {
    asm volatile(
        "mma.sync.aligned.m16n8k16.row.col.f32.f16.f16.f32 "
        "{%0,%1,%2,%3}, {%4,%5,%6,%7}, {%8,%9}, {%0,%1,%2,%3};"
        : "+f"(c[0]), "+f"(c[1]), "+f"(c[2]), "+f"(c[3])
        : "r"(a0), "r"(a1), "r"(a2), "r"(a3), "r"(b0), "r"(b1));
}
__device__ __forceinline__ void ldsm_x4(uint32_t* r, uint32_t addr) {
    asm volatile(
        "ldmatrix.sync.aligned.m8n8.x4.shared.b16 {%0,%1,%2,%3}, [%4];"
        : "=r"(r[0]), "=r"(r[1]), "=r"(r[2]), "=r"(r[3]) : "r"(addr));
}

// ---------------------------------------------------------------------------
__global__ void dummy_kernel() {}

// K0: zero agg (d_out) + denom
__global__ void zero_kernel(float4* __restrict__ out4) {
    int idx = blockIdx.x * blockDim.x + threadIdx.x;
    int stride = gridDim.x * blockDim.x;
    const int n4 = N_NODES * DIM / 4;
    float4 z = make_float4(0.f, 0.f, 0.f, 0.f);
    for (int i = idx; i < n4; i += stride) out4[i] = z;
    for (int i = idx; i < N_NODES; i += stride) g_denom[i] = 0.f;
}

// ---------------------------------------------------------------------------
// K1: 4 edges/warp (8 lanes each), fp32 gathers (R9 known-best: 67.8us)
// ---------------------------------------------------------------------------
__global__ void edge_kernel(const float4* __restrict__ emb4,
                            const int* __restrict__ edges,
                            float* __restrict__ agg) {
    int gwarp = (blockIdx.x * blockDim.x + threadIdx.x) >> 5;
    int lane = threadIdx.x & 31;
    int q = lane >> 3;
    int ql = lane & 7;

    int e = gwarp * 4 + q;
    if (e >= N_EDGES) return;

    int r = edges[e];
    int c = edges[N_EDGES + e];
    if ((unsigned)r >= N_NODES || (unsigned)c >= N_NODES) return;

    const float4* ar = emb4 + (size_t)r * 32;
    const float4* br = emb4 + (size_t)c * 32;
    float4 a[4], b[4];
#pragma unroll
    for (int j = 0; j < 4; j++) {
        a[j] = ar[ql + 8 * j];
        b[j] = br[ql + 8 * j];
    }

    float p = 0.f;
#pragma unroll
    for (int j = 0; j < 4; j++)
        p += a[j].x * b[j].x + a[j].y * b[j].y + a[j].z * b[j].z +
             a[j].w * b[j].w;
#pragma unroll
    for (int o = 4; o > 0; o >>= 1)
        p += __shfl_xor_sync(0xffffffffu, p, o);

    float w = expf(p);
    if (ql == 0) atomicAdd(&g_denom[r], w);

#pragma unroll
    for (int j = 0; j < 4; j++) {
        float* dst = agg + (size_t)r * DIM + (ql + 8 * j) * 4;
        asm volatile("red.global.add.v4.f32 [%0], {%1, %2, %3, %4};"
                     :: "l"(dst), "f"(w * b[j].x), "f"(w * b[j].y),
                        "f"(w * b[j].z), "f"(w * b[j].w)
                     : "memory");
    }
}

// ---------------------------------------------------------------------------
// K2: fp16 2-term MMA GEMM + LN with register epilogue.
//   D = xh*fp16(W) + (256*xl)*fp16(W/256)
// ---------------------------------------------------------------------------
#define TILE_R 64
#define WSTRIDE 132
#define SM_WPH 0
#define SM_WP2 (128 * WSTRIDE)
#define SM_XPH (2 * 128 * WSTRIDE)
#define SM_XP2 (2 * 128 * WSTRIDE + 64 * WSTRIDE)
#define SM_PS (2 * 128 * WSTRIDE + 2 * 64 * WSTRIDE)   // float2[2][64] = 256 w
#define SM_BIAS (SM_PS + 256)
#define SM_GAM (SM_BIAS + 128)
#define SM_BET (SM_GAM + 128)
#define SMEM_WORDS (SM_BET + 128)
#define GEMM_SMEM_BYTES (SMEM_WORDS * 4)

__global__ void __launch_bounds__(256, 1)
gemm_ln_kernel(const float* __restrict__ emb,
               const float* __restrict__ W,
               const float* __restrict__ bias,
               const float* __restrict__ gamma,
               const float* __restrict__ beta,
               float* __restrict__ out) {
    extern __shared__ uint32_t smem[];
    uint32_t* Wph = smem + SM_WPH;
    uint32_t* Wp2 = smem + SM_WP2;
    uint32_t* xph = smem + SM_XPH;
    uint32_t* xp2 = smem + SM_XP2;
    float2* ps = reinterpret_cast<float2*>(smem + SM_PS);
    float* sBias = reinterpret_cast<float*>(smem + SM_BIAS);
    float* sGam = reinterpret_cast<float*>(smem + SM_GAM);
    float* sBet = reinterpret_cast<float*>(smem + SM_BET);

    const int tid = threadIdx.x;
    const int lane = tid & 31;
    const int wid = tid >> 5;
    const int g = lane >> 2;
    const int tig = lane & 3;

    for (int i = tid; i < 128; i += 256) {
        sBias[i] = bias[i];
        sGam[i] = gamma[i];
        sBet[i] = beta[i];
    }
    for (int idx = tid; idx < 128 * 128; idx += 256) {
        int n = idx >> 7;
        int k2 = idx & 127;
        float2 w2 = *reinterpret_cast<const float2*>(&W[n * 256 + 2 * k2]);
        Wph[n * WSTRIDE + k2] = pack2h(w2.x, w2.y);
        Wp2[n * WSTRIDE + k2] =
            pack2h(w2.x * (1.0f / 256.0f), w2.y * (1.0f / 256.0f));
    }
    __syncthreads();

    const int mwarp = wid & 3;
    const int nwarp = wid >> 2;
    const int n0 = nwarp * 64;
    const int r0l = mwarp * 16 + g;   // local tile row of fragment rows 0/1
    const int r1l = r0l + 8;

    // ldmatrix addresses
    const uint32_t sb = smem_u32(smem);
    const int rowA = mwarp * 16 + (lane & 15);
    const int colwA = (lane >> 4) * 4;
    const uint32_t aAh0 = sb + (SM_XPH + rowA * WSTRIDE + colwA) * 4;
    const uint32_t aA20 = sb + (SM_XP2 + rowA * WSTRIDE + colwA) * 4;
    const int rowB = n0 + (lane & 7) + ((lane & 16) >> 1);
    const int colwB = ((lane >> 3) & 1) * 4;
    const uint32_t aBh0 = sb + (SM_WPH + rowB * WSTRIDE + colwB) * 4;
    const uint32_t aB20 = sb + (SM_WP2 + rowB * WSTRIDE + colwB) * 4;
    const uint32_t NTP_STEP = 16 * WSTRIDE * 4;

    const int ntiles = (N_NODES + TILE_R - 1) / TILE_R;
    for (int tile = blockIdx.x; tile < ntiles; tile += gridDim.x) {
        const int row0 = tile * TILE_R;

        // ---- stage x tile ----
#pragma unroll
        for (int i = 0; i < 8; i++) {
            int r = wid * 8 + i;
            int row = row0 + r;
            float4 e4, a4;
            if (row < N_NODES) {
                e4 = reinterpret_cast<const float4*>(emb)[(size_t)row * 32 + lane];
                float inv_d = 1.0f / (g_denom[row] + 1e-20f);
                a4 = reinterpret_cast<const float4*>(out)[(size_t)row * 32 + lane];
                a4.x *= inv_d; a4.y *= inv_d; a4.z *= inv_d; a4.w *= inv_d;
            } else {
                e4 = make_float4(0.f, 0.f, 0.f, 0.f);
                a4 = e4;
            }
            float ex = __half2float(__float2half_rn(e4.x));
            float ey = __half2float(__float2half_rn(e4.y));
            float ez = __half2float(__float2half_rn(e4.z));
            float ew = __half2float(__float2half_rn(e4.w));
            xph[r * WSTRIDE + 2 * lane] = pack2h(ex, ey);
            xph[r * WSTRIDE + 2 * lane + 1] = pack2h(ez, ew);
            xp2[r * WSTRIDE + 2 * lane] =
                pack2h((e4.x - ex) * 256.0f, (e4.y - ey) * 256.0f);
            xp2[r * WSTRIDE + 2 * lane + 1] =
                pack2h((e4.z - ez) * 256.0f, (e4.w - ew) * 256.0f);

            float ax = __half2float(__float2half_rn(a4.x));
            float ay = __half2float(__float2half_rn(a4.y));
            float az = __half2float(__float2half_rn(a4.z));
            float aw = __half2float(__float2half_rn(a4.w));
            xph[r * WSTRIDE + 64 + 2 * lane] = pack2h(ax, ay);
            xph[r * WSTRIDE + 64 + 2 * lane + 1] = pack2h(az, aw);
            xp2[r * WSTRIDE + 64 + 2 * lane] =
                pack2h((a4.x - ax) * 256.0f, (a4.y - ay) * 256.0f);
            xp2[r * WSTRIDE + 64 + 2 * lane + 1] =
                pack2h((a4.z - az) * 256.0f, (a4.w - aw) * 256.0f);
        }
        __syncthreads();

        // ---- mma mainloop ----
        float acc[8][4];
#pragma unroll
        for (int nt = 0; nt < 8; nt++)
#pragma unroll
            for (int qq = 0; qq < 4; qq++) acc[nt][qq] = 0.f;

        uint32_t aAh = aAh0, aA2 = aA20, aBh = aBh0, aB2 = aB20;
#pragma unroll
        for (int ks = 0; ks < 16; ks++) {
            uint32_t ah[4], al[4];
            ldsm_x4(ah, aAh);
            ldsm_x4(al, aA2);
            aAh += 32; aA2 += 32;
#pragma unroll
            for (int ntp = 0; ntp < 4; ntp++) {
                uint32_t bh[4], b2[4];
                ldsm_x4(bh, aBh + ntp * NTP_STEP);
                ldsm_x4(b2, aB2 + ntp * NTP_STEP);
                mma_fp16(acc[2 * ntp], ah[0], ah[1], ah[2], ah[3], bh[0], bh[1]);
                mma_fp16(acc[2 * ntp + 1], ah[0], ah[1], ah[2], ah[3], bh[2], bh[3]);
                mma_fp16(acc[2 * ntp], al[0], al[1], al[2], al[3], b2[0], b2[1]);
                mma_fp16(acc[2 * ntp + 1], al[0], al[1], al[2], al[3], b2[2], b2[3]);
            }
            aBh += 32; aB2 += 32;
        }

        // ---- register epilogue: bias + per-row stats ----
        float s0 = 0.f, sq0 = 0.f, s1 = 0.f, sq1 = 0.f;
#pragma unroll
        for (int nt = 0; nt < 8; nt++) {
            int c = n0 + nt * 8 + 2 * tig;
            float2 bb = *reinterpret_cast<const float2*>(&sBias[c]);
            acc[nt][0] += bb.x; acc[nt][1] += bb.y;
            acc[nt][2] += bb.x; acc[nt][3] += bb.y;
            s0 += acc[nt][0] + acc[nt][1];
            sq0 += acc[nt][0] * acc[nt][0] + acc[nt][1] * acc[nt][1];
            s1 += acc[nt][2] + acc[nt][3];
            sq1 += acc[nt][2] * acc[nt][2] + acc[nt][3] * acc[nt][3];
        }
#pragma unroll
        for (int o = 1; o <= 2; o <<= 1) {
            s0 += __shfl_xor_sync(0xffffffffu, s0, o);
            sq0 += __shfl_xor_sync(0xffffffffu, sq0, o);
            s1 += __shfl_xor_sync(0xffffffffu, s1, o);
            sq1 += __shfl_xor_sync(0xffffffffu, sq1, o);
        }
        if (tig == 0) {
            ps[nwarp * 64 + r0l] = make_float2(s0, sq0);
            ps[nwarp * 64 + r1l] = make_float2(s1, sq1);
        }
        __syncthreads();
        {
            float2 o0 = ps[(1 - nwarp) * 64 + r0l];
            float2 o1 = ps[(1 - nwarp) * 64 + r1l];
            s0 += o0.x; sq0 += o0.y;
            s1 += o1.x; sq1 += o1.y;
        }
        float mu0 = s0 * (1.0f / 128.0f);
        float rs0 = rsqrtf(sq0 * (1.0f / 128.0f) - mu0 * mu0 + 1e-5f);
        float mu1 = s1 * (1.0f / 128.0f);
        float rs1 = rsqrtf(sq1 * (1.0f / 128.0f) - mu1 * mu1 + 1e-5f);

        const int gr0 = row0 + r0l;
        const int gr1 = row0 + r1l;
        const bool ok0 = gr0 < N_NODES;
        const bool ok1 = gr1 < N_NODES;
#pragma unroll
        for (int nt = 0; nt < 8; nt++) {
            int c = n0 + nt * 8 + 2 * tig;
            float2 gg = *reinterpret_cast<const float2*>(&sGam[c]);
            float2 be = *reinterpret_cast<const float2*>(&sBet[c]);
            if (ok0) {
                float2 v;
                v.x = (acc[nt][0] - mu0) * rs0 * gg.x + be.x;
                v.y = (acc[nt][1] - mu0) * rs0 * gg.y + be.y;
                *reinterpret_cast<float2*>(out + (size_t)gr0 * 128 + c) = v;
            }
            if (ok1) {
                float2 v;
                v.x = (acc[nt][2] - mu1) * rs1 * gg.x + be.x;
                v.y = (acc[nt][3] - mu1) * rs1 * gg.y + be.y;
                *reinterpret_cast<float2*>(out + (size_t)gr1 * 128 + c) = v;
            }
        }
        // next tile's staging sync (top of loop) orders xs/ps reuse
    }
}

// ---------------------------------------------------------------------------
extern "C" void kernel_launch(void* const* d_in, const int* in_sizes, int n_in,
                              void* d_out, int out_size) {
    const float* emb = (const float*)d_in[0];
    const int* edges = (const int*)d_in[1];  // int32 (JAX x64 disabled)
    const float* W = (const float*)d_in[2];
    const float* bias = (const float*)d_in[3];
    const float* gamma = (const float*)d_in[4];
    const float* beta = (const float*)d_in[5];
    float* out = (float*)d_out;

    (void)in_sizes; (void)n_in; (void)out_size;

    // ncu captures global launch #4 -> place gemm_ln there this round.
    zero_kernel<<<4096, 256>>>(reinterpret_cast<float4*>(out));  // #1

    {  // #2: edge kernel, 4 edges per warp, fp32 gathers
        int nwarps = N_EDGES / 4;
        int blocks = (nwarps * 32 + 255) / 256;
        edge_kernel<<<blocks, 256>>>(reinterpret_cast<const float4*>(emb),
                                     edges, out);
    }

    dummy_kernel<<<1, 32>>>();  // #3

    // #4: GEMM + LN (register epilogue)
    cudaFuncSetAttribute(gemm_ln_kernel,
                         cudaFuncAttributeMaxDynamicSharedMemorySize,
                         GEMM_SMEM_BYTES);
    gemm_ln_kernel<<<148, 256, GEMM_SMEM_BYTES>>>(emb, W, bias, gamma, beta,
                                                  out);
}

// round 12
// speedup vs baseline: 1.3562x; 1.0822x over previous
#include <cuda_runtime.h>
#include <cuda_fp16.h>
#include <cstdint>

#define N_NODES 50000
#define N_EDGES 600000
#define DIM 128

__device__ float g_denom[N_NODES];

// ---------------------------------------------------------------------------
// helpers
// ---------------------------------------------------------------------------
__device__ __forceinline__ uint32_t pack2h(float x0, float x1) {
    uint32_t d;
    asm("cvt.rn.f16x2.f32 %0, %1, %2;" : "=r"(d) : "f"(x1), "f"(x0));
    return d;
}
__device__ __forceinline__ uint32_t smem_u32(const void* p) {
    uint32_t a;
    asm("{ .reg .u64 t; cvta.to.shared.u64 t, %1; cvt.u32.u64 %0, t; }"
        : "=r"(a) : "l"(p));
    return a;
}
__device__ __forceinline__ void mma_fp16(float* c, uint32_t a0, uint32_t a1,
                                         uint32_t a2, uint32_t a3,
                                         uint32_t b0, uint32_t b1) {
    asm volatile(
        "mma.sync.aligned.m16n8k16.row.col.f32.f16.f16.f32 "
        "{%0,%1,%2,%3}, {%4,%5,%6,%7}, {%8,%9}, {%0,%1,%2,%3};"
        : "+f"(c[0]), "+f"(c[1]), "+f"(c[2]), "+f"(c[3])
        : "r"(a0), "r"(a1), "r"(a2), "r"(a3), "r"(b0), "r"(b1));
}
__device__ __forceinline__ void ldsm_x4(uint32_t* r, uint32_t addr) {
    asm volatile(
        "ldmatrix.sync.aligned.m8n8.x4.shared.b16 {%0,%1,%2,%3}, [%4];"
        : "=r"(r[0]), "=r"(r[1]), "=r"(r[2]), "=r"(r[3]) : "r"(addr));
}

// ---------------------------------------------------------------------------
__global__ void dummy_kernel() {}

// K0: zero agg (d_out) + denom
__global__ void zero_kernel(float4* __restrict__ out4) {
    int idx = blockIdx.x * blockDim.x + threadIdx.x;
    int stride = gridDim.x * blockDim.x;
    const int n4 = N_NODES * DIM / 4;
    float4 z = make_float4(0.f, 0.f, 0.f, 0.f);
    for (int i = idx; i < n4; i += stride) out4[i] = z;
    for (int i = idx; i < N_NODES; i += stride) g_denom[i] = 0.f;
}

// ---------------------------------------------------------------------------
// K1: 4 edges/warp (8 lanes each), fp32 gathers (67.8us, at atomic floor)
// ---------------------------------------------------------------------------
__global__ void edge_kernel(const float4* __restrict__ emb4,
                            const int* __restrict__ edges,
                            float* __restrict__ agg) {
    int gwarp = (blockIdx.x * blockDim.x + threadIdx.x) >> 5;
    int lane = threadIdx.x & 31;
    int q = lane >> 3;
    int ql = lane & 7;

    int e = gwarp * 4 + q;
    if (e >= N_EDGES) return;

    int r = edges[e];
    int c = edges[N_EDGES + e];
    if ((unsigned)r >= N_NODES || (unsigned)c >= N_NODES) return;

    const float4* ar = emb4 + (size_t)r * 32;
    const float4* br = emb4 + (size_t)c * 32;
    float4 a[4], b[4];
#pragma unroll
    for (int j = 0; j < 4; j++) {
        a[j] = ar[ql + 8 * j];
        b[j] = br[ql + 8 * j];
    }

    float p = 0.f;
#pragma unroll
    for (int j = 0; j < 4; j++)
        p += a[j].x * b[j].x + a[j].y * b[j].y + a[j].z * b[j].z +
             a[j].w * b[j].w;
#pragma unroll
    for (int o = 4; o > 0; o >>= 1)
        p += __shfl_xor_sync(0xffffffffu, p, o);

    float w = expf(p);
    if (ql == 0) atomicAdd(&g_denom[r], w);

#pragma unroll
    for (int j = 0; j < 4; j++) {
        float* dst = agg + (size_t)r * DIM + (ql + 8 * j) * 4;
        asm volatile("red.global.add.v4.f32 [%0], {%1, %2, %3, %4};"
                     :: "l"(dst), "f"(w * b[j].x), "f"(w * b[j].y),
                        "f"(w * b[j].z), "f"(w * b[j].w)
                     : "memory");
    }
}

// ---------------------------------------------------------------------------
// K2: fp16 2-term MMA GEMM + LN, 512 threads (16 warps) for latency hiding.
//   D = xh*fp16(W) + (256*xl)*fp16(W/256)
// warp w: rows 16*(w&3), cols 32*(w>>2). Register epilogue, ps[4][64] exchange.
// ---------------------------------------------------------------------------
#define TILE_R 64
#define WSTRIDE 132
#define SM_WPH 0
#define SM_WP2 (128 * WSTRIDE)
#define SM_XPH (2 * 128 * WSTRIDE)
#define SM_XP2 (2 * 128 * WSTRIDE + 64 * WSTRIDE)
#define SM_PS (2 * 128 * WSTRIDE + 2 * 64 * WSTRIDE)  // float2[4][64] = 512 w
#define SM_BIAS (SM_PS + 512)
#define SM_GAM (SM_BIAS + 128)
#define SM_BET (SM_GAM + 128)
#define SMEM_WORDS (SM_BET + 128)
#define GEMM_SMEM_BYTES (SMEM_WORDS * 4)

__global__ void __launch_bounds__(512, 1)
gemm_ln_kernel(const float* __restrict__ emb,
               const float* __restrict__ W,
               const float* __restrict__ bias,
               const float* __restrict__ gamma,
               const float* __restrict__ beta,
               float* __restrict__ out) {
    extern __shared__ uint32_t smem[];
    uint32_t* Wph = smem + SM_WPH;
    uint32_t* Wp2 = smem + SM_WP2;
    uint32_t* xph = smem + SM_XPH;
    uint32_t* xp2 = smem + SM_XP2;
    float2* ps = reinterpret_cast<float2*>(smem + SM_PS);
    float* sBias = reinterpret_cast<float*>(smem + SM_BIAS);
    float* sGam = reinterpret_cast<float*>(smem + SM_GAM);
    float* sBet = reinterpret_cast<float*>(smem + SM_BET);

    const int tid = threadIdx.x;
    const int lane = tid & 31;
    const int wid = tid >> 5;   // 0..15
    const int g = lane >> 2;
    const int tig = lane & 3;

    for (int i = tid; i < 128; i += 512) {
        sBias[i] = bias[i];
        sGam[i] = gamma[i];
        sBet[i] = beta[i];
    }
    for (int idx = tid; idx < 128 * 128; idx += 512) {
        int n = idx >> 7;
        int k2 = idx & 127;
        float2 w2 = *reinterpret_cast<const float2*>(&W[n * 256 + 2 * k2]);
        Wph[n * WSTRIDE + k2] = pack2h(w2.x, w2.y);
        Wp2[n * WSTRIDE + k2] =
            pack2h(w2.x * (1.0f / 256.0f), w2.y * (1.0f / 256.0f));
    }
    __syncthreads();

    const int mwarp = wid & 3;   // row group: rows 16*mwarp .. +15
    const int nwarp = wid >> 2;  // col quarter: cols 32*nwarp .. +31
    const int n0 = nwarp * 32;
    const int r0l = mwarp * 16 + g;
    const int r1l = r0l + 8;

    // ldmatrix addresses
    const uint32_t sb = smem_u32(smem);
    const int rowA = mwarp * 16 + (lane & 15);
    const int colwA = (lane >> 4) * 4;
    const uint32_t aAh0 = sb + (SM_XPH + rowA * WSTRIDE + colwA) * 4;
    const uint32_t aA20 = sb + (SM_XP2 + rowA * WSTRIDE + colwA) * 4;
    const int rowB = n0 + (lane & 7) + ((lane & 16) >> 1);
    const int colwB = ((lane >> 3) & 1) * 4;
    const uint32_t aBh0 = sb + (SM_WPH + rowB * WSTRIDE + colwB) * 4;
    const uint32_t aB20 = sb + (SM_WP2 + rowB * WSTRIDE + colwB) * 4;
    const uint32_t NTP_STEP = 16 * WSTRIDE * 4;

    const int ntiles = (N_NODES + TILE_R - 1) / TILE_R;
    for (int tile = blockIdx.x; tile < ntiles; tile += gridDim.x) {
        const int row0 = tile * TILE_R;

        // ---- stage x tile: warp wid stages rows wid*4 .. wid*4+3 ----
#pragma unroll
        for (int i = 0; i < 4; i++) {
            int r = wid * 4 + i;
            int row = row0 + r;
            float4 e4, a4;
            if (row < N_NODES) {
                e4 = reinterpret_cast<const float4*>(emb)[(size_t)row * 32 + lane];
                float inv_d = 1.0f / (g_denom[row] + 1e-20f);
                a4 = reinterpret_cast<const float4*>(out)[(size_t)row * 32 + lane];
                a4.x *= inv_d; a4.y *= inv_d; a4.z *= inv_d; a4.w *= inv_d;
            } else {
                e4 = make_float4(0.f, 0.f, 0.f, 0.f);
                a4 = e4;
            }
            float ex = __half2float(__float2half_rn(e4.x));
            float ey = __half2float(__float2half_rn(e4.y));
            float ez = __half2float(__float2half_rn(e4.z));
            float ew = __half2float(__float2half_rn(e4.w));
            xph[r * WSTRIDE + 2 * lane] = pack2h(ex, ey);
            xph[r * WSTRIDE + 2 * lane + 1] = pack2h(ez, ew);
            xp2[r * WSTRIDE + 2 * lane] =
                pack2h((e4.x - ex) * 256.0f, (e4.y - ey) * 256.0f);
            xp2[r * WSTRIDE + 2 * lane + 1] =
                pack2h((e4.z - ez) * 256.0f, (e4.w - ew) * 256.0f);

            float ax = __half2float(__float2half_rn(a4.x));
            float ay = __half2float(__float2half_rn(a4.y));
            float az = __half2float(__float2half_rn(a4.z));
            float aw = __half2float(__float2half_rn(a4.w));
            xph[r * WSTRIDE + 64 + 2 * lane] = pack2h(ax, ay);
            xph[r * WSTRIDE + 64 + 2 * lane + 1] = pack2h(az, aw);
            xp2[r * WSTRIDE + 64 + 2 * lane] =
                pack2h((a4.x - ax) * 256.0f, (a4.y - ay) * 256.0f);
            xp2[r * WSTRIDE + 64 + 2 * lane + 1] =
                pack2h((a4.z - az) * 256.0f, (a4.w - aw) * 256.0f);
        }
        __syncthreads();

        // ---- mma mainloop: warp covers 16 rows x 32 cols ----
        float acc[4][4];
#pragma unroll
        for (int nt = 0; nt < 4; nt++)
#pragma unroll
            for (int qq = 0; qq < 4; qq++) acc[nt][qq] = 0.f;

        uint32_t aAh = aAh0, aA2 = aA20, aBh = aBh0, aB2 = aB20;
#pragma unroll
        for (int ks = 0; ks < 16; ks++) {
            uint32_t ah[4], al[4];
            ldsm_x4(ah, aAh);
            ldsm_x4(al, aA2);
            aAh += 32; aA2 += 32;
#pragma unroll
            for (int ntp = 0; ntp < 2; ntp++) {
                uint32_t bh[4], b2[4];
                ldsm_x4(bh, aBh + ntp * NTP_STEP);
                ldsm_x4(b2, aB2 + ntp * NTP_STEP);
                mma_fp16(acc[2 * ntp], ah[0], ah[1], ah[2], ah[3], bh[0], bh[1]);
                mma_fp16(acc[2 * ntp + 1], ah[0], ah[1], ah[2], ah[3], bh[2], bh[3]);
                mma_fp16(acc[2 * ntp], al[0], al[1], al[2], al[3], b2[0], b2[1]);
                mma_fp16(acc[2 * ntp + 1], al[0], al[1], al[2], al[3], b2[2], b2[3]);
            }
            aBh += 32; aB2 += 32;
        }

        // ---- register epilogue: bias + per-row stats ----
        float s0 = 0.f, sq0 = 0.f, s1 = 0.f, sq1 = 0.f;
#pragma unroll
        for (int nt = 0; nt < 4; nt++) {
            int c = n0 + nt * 8 + 2 * tig;
            float2 bb = *reinterpret_cast<const float2*>(&sBias[c]);
            acc[nt][0] += bb.x; acc[nt][1] += bb.y;
            acc[nt][2] += bb.x; acc[nt][3] += bb.y;
            s0 += acc[nt][0] + acc[nt][1];
            sq0 += acc[nt][0] * acc[nt][0] + acc[nt][1] * acc[nt][1];
            s1 += acc[nt][2] + acc[nt][3];
            sq1 += acc[nt][2] * acc[nt][2] + acc[nt][3] * acc[nt][3];
        }
#pragma unroll
        for (int o = 1; o <= 2; o <<= 1) {
            s0 += __shfl_xor_sync(0xffffffffu, s0, o);
            sq0 += __shfl_xor_sync(0xffffffffu, sq0, o);
            s1 += __shfl_xor_sync(0xffffffffu, s1, o);
            sq1 += __shfl_xor_sync(0xffffffffu, sq1, o);
        }
        if (tig == 0) {
            ps[nwarp * 64 + r0l] = make_float2(s0, sq0);
            ps[nwarp * 64 + r1l] = make_float2(s1, sq1);
        }
        __syncthreads();
#pragma unroll
        for (int k = 1; k < 4; k++) {
            int nw = (nwarp + k) & 3;
            float2 o0 = ps[nw * 64 + r0l];
            float2 o1 = ps[nw * 64 + r1l];
            s0 += o0.x; sq0 += o0.y;
            s1 += o1.x; sq1 += o1.y;
        }
        float mu0 = s0 * (1.0f / 128.0f);
        float rs0 = rsqrtf(sq0 * (1.0f / 128.0f) - mu0 * mu0 + 1e-5f);
        float mu1 = s1 * (1.0f / 128.0f);
        float rs1 = rsqrtf(sq1 * (1.0f / 128.0f) - mu1 * mu1 + 1e-5f);

        const int gr0 = row0 + r0l;
        const int gr1 = row0 + r1l;
        const bool ok0 = gr0 < N_NODES;
        const bool ok1 = gr1 < N_NODES;
#pragma unroll
        for (int nt = 0; nt < 4; nt++) {
            int c = n0 + nt * 8 + 2 * tig;
            float2 gg = *reinterpret_cast<const float2*>(&sGam[c]);
            float2 be = *reinterpret_cast<const float2*>(&sBet[c]);
            if (ok0) {
                float2 v;
                v.x = (acc[nt][0] - mu0) * rs0 * gg.x + be.x;
                v.y = (acc[nt][1] - mu0) * rs0 * gg.y + be.y;
                *reinterpret_cast<float2*>(out + (size_t)gr0 * 128 + c) = v;
            }
            if (ok1) {
                float2 v;
                v.x = (acc[nt][2] - mu1) * rs1 * gg.x + be.x;
                v.y = (acc[nt][3] - mu1) * rs1 * gg.y + be.y;
                *reinterpret_cast<float2*>(out + (size_t)gr1 * 128 + c) = v;
            }
        }
        // staging sync at next loop top orders xph/ps reuse
    }
}

// ---------------------------------------------------------------------------
extern "C" void kernel_launch(void* const* d_in, const int* in_sizes, int n_in,
                              void* d_out, int out_size) {
    const float* emb = (const float*)d_in[0];
    const int* edges = (const int*)d_in[1];  // int32 (JAX x64 disabled)
    const float* W = (const float*)d_in[2];
    const float* bias = (const float*)d_in[3];
    const float* gamma = (const float*)d_in[4];
    const float* beta = (const float*)d_in[5];
    float* out = (float*)d_out;

    (void)in_sizes; (void)n_in; (void)out_size;

    // ncu captures global launch #4 -> keep gemm_ln there.
    zero_kernel<<<4096, 256>>>(reinterpret_cast<float4*>(out));  // #1

    {  // #2: edge kernel
        int nwarps = N_EDGES / 4;
        int blocks = (nwarps * 32 + 255) / 256;
        edge_kernel<<<blocks, 256>>>(reinterpret_cast<const float4*>(emb),
                                     edges, out);
    }

    dummy_kernel<<<1, 32>>>();  // #3

    // #4: GEMM + LN (512 threads, 16 warps)
    cudaFuncSetAttribute(gemm_ln_kernel,
                         cudaFuncAttributeMaxDynamicSharedMemorySize,
                         GEMM_SMEM_BYTES);
    gemm_ln_kernel<<<148, 512, GEMM_SMEM_BYTES>>>(emb, W, bias, gamma, beta,
                                                  out);
}